// round 17
// baseline (speedup 1.0000x reference)
#include <cuda_runtime.h>
#include <cstdint>

// ============================================================================
// CrossAttMultiplexer — analytic collapse + 256-bit memory ops (v8 family)
//
//   scores[n,i,j] = (WQ.WK)/sqrt(d) * x[n,i] * s[n,j]  (rank-1)
//   alpha = softmax(scores, -1)
//   out[n,i] = v[n,i] * sum_j alpha[n,i,j] = s[n,i] * WV[0]
// Attention cancels identically (softmax row-sum == 1). Mandatory traffic:
// read s + write out = 12.6MB.
//
// R17: v8 family is the replicated winner (6.624, 6.624, 6.592 vs the
// 6.85-6.91 band of all non-v8 configs; kernel dur 5.31us). R16 showed TLP
// (196,608 threads, BATCH=1) beats ILP. This round repartitions the same
// threads into fatter CTAs: 192 CTAs x 1024 thr (vs 768 x 256) — identical
// per-thread work and instruction mix, 4x fewer CTA dispatches.
//   - ld.global.v8.f32 (default cache: s stays L2-resident across replays)
//   - st.global.cs.v8.f32 (streaming: out evict-first)
// ============================================================================

#define THREADS 1024

struct __align__(32) f8 { float a0,a1,a2,a3,a4,a5,a6,a7; };

__device__ __forceinline__ f8 ldg256(const f8* p) {
    f8 r;
    asm volatile(
        "ld.global.v8.f32 {%0,%1,%2,%3,%4,%5,%6,%7}, [%8];"
        : "=f"(r.a0), "=f"(r.a1), "=f"(r.a2), "=f"(r.a3),
          "=f"(r.a4), "=f"(r.a5), "=f"(r.a6), "=f"(r.a7)
        : "l"(p));
    return r;
}

__device__ __forceinline__ void stg256_cs(f8* p, const f8& v) {
    asm volatile(
        "st.global.cs.v8.f32 [%0], {%1,%2,%3,%4,%5,%6,%7,%8};"
        :: "l"(p),
           "f"(v.a0), "f"(v.a1), "f"(v.a2), "f"(v.a3),
           "f"(v.a4), "f"(v.a5), "f"(v.a6), "f"(v.a7)
        : "memory");
}

__global__ void __launch_bounds__(THREADS)
scale_v8_fat_kernel(const f8* __restrict__ s8,
                    const float* __restrict__ WV,
                    f8* __restrict__ out8) {
    const float wv = __ldg(WV);
    int i = blockIdx.x * THREADS + threadIdx.x;

    f8 v = ldg256(&s8[i]);
    v.a0 *= wv; v.a1 *= wv; v.a2 *= wv; v.a3 *= wv;
    v.a4 *= wv; v.a5 *= wv; v.a6 *= wv; v.a7 *= wv;
    stg256_cs(&out8[i], v);
}

// Generic fallback (bounds-checked, grid-stride) for sizes that don't tile.
__global__ void scale_generic_kernel(const float* __restrict__ s,
                                     const float* __restrict__ WV,
                                     float* __restrict__ out, int n) {
    const float wv = WV[0];
    for (int i = blockIdx.x * blockDim.x + threadIdx.x; i < n;
         i += gridDim.x * blockDim.x)
        out[i] = s[i] * wv;
}

extern "C" void kernel_launch(void* const* d_in, const int* in_sizes, int n_in,
                              void* d_out, int out_size) {
    // metadata order: x, s, WQ, WK, WV
    const float* s  = (const float*)d_in[1];
    const float* WV = (const float*)d_in[4];
    float* out = (float*)d_out;

    int n = out_size;                               // 1,572,864 expected
    const int tile = THREADS * 8;                   // 8192 elements per CTA
    if ((n % tile) == 0 &&
        (((uintptr_t)s | (uintptr_t)out) & 31) == 0) {
        int blocks = n / tile;                      // 192
        scale_v8_fat_kernel<<<blocks, THREADS>>>((const f8*)s, WV, (f8*)out);
    } else {
        int blocks = (n + 255) / 256;
        if (blocks > 1184) blocks = 1184;
        scale_generic_kernel<<<blocks, 256>>>(s, WV, out, n);
    }
}